// round 4
// baseline (speedup 1.0000x reference)
#include <cuda_runtime.h>

// SSIM loss, (32,1,512,512) fp32. Single fused kernel, f32x2-packed FIR.
// R4: tile 32x32 (single-phase), smem ~31.6KB -> 6 blocks/SM, 2x2-px vertical
//     pass with LDS.128 reads, fused last-block mean.

#define IMG   512
#define TS    32
#define SR    42          // TS + 10 staged rows
#define SCF2  42          // staged cols as float2 (TS + 10)
#define SPIT  42          // stage pitch (f2): 336B -> lane stride 20 banks, clean
#define HPIT  34          // hxy pitch (f2): 272B
#define PPIT  36          // hp  pitch (f32): 144B
#define GX    16
#define GY    16
#define GZ    32
#define NBLK  (GX * GY * GZ)   // 8192

__device__ float        g_partials[NBLK];
__device__ unsigned int g_count;     // zero-init; self-resets

// normalized 1D Gaussian, K=11, sigma=1.5
#define W0 0.00102838f
#define W1 0.00759876f
#define W2 0.03600077f
#define W3 0.10936060f
#define W4 0.21300553f
#define W5 0.26601172f

#define FMA2(d, a, b, c) \
    asm("fma.rn.f32x2 %0, %1, %2, %3;" : "=l"(d) : "l"(a), "l"(b), "l"(c))
#define UNPK(lo, hi, v) \
    asm("mov.b64 {%0, %1}, %2;" : "=f"(lo), "=f"(hi) : "l"(v))

__device__ __forceinline__ unsigned long long pk2(float w) {
    unsigned long long r;
    asm("mov.b64 %0, {%1, %1};" : "=l"(r) : "f"(w));
    return r;
}

__global__ __launch_bounds__(256, 6)
void ssim_fused_kernel(const float* __restrict__ X, const float* __restrict__ Y,
                       float* __restrict__ out)
{
    __shared__ unsigned long long sxy[SR][SPIT];   // packed (x,y)  14.1KB
    __shared__ unsigned long long hxy[SR][HPIT];   // h-conv (x,y)  11.4KB
    __shared__ float              hp [SR][PPIT];   // h-conv (x*y)   6.0KB
    __shared__ float              wsum[8];
    __shared__ int                s_last;

    const float WGs[11] = {W0, W1, W2, W3, W4, W5, W4, W3, W2, W1, W0};
    const unsigned long long p0 = pk2(W0), p1 = pk2(W1), p2 = pk2(W2),
                             p3 = pk2(W3), p4 = pk2(W4), p5 = pk2(W5);
    const unsigned long long WP[11] = {p0,p1,p2,p3,p4,p5,p4,p3,p2,p1,p0};

    const int tid  = threadIdx.x;
    const int img  = blockIdx.z;
    const int row0 = blockIdx.y * TS - 5;
    const int col0 = blockIdx.x * TS - 5;

    const float* __restrict__ Xi = X + (size_t)img * IMG * IMG;
    const float* __restrict__ Yi = Y + (size_t)img * IMG * IMG;

    // ---------------- stage packed (x, y) ----------------
    const bool interior = (row0 >= 0) && (row0 + SR <= IMG) &&
                          (col0 >= 0) && (col0 + SCF2 <= IMG);
    if (interior) {
        #pragma unroll 1
        for (int i = tid; i < SR * SCF2; i += 256) {
            int r = i / SCF2;
            int c = i - r * SCF2;
            const int g = (row0 + r) * IMG + (col0 + c);
            float xv = __ldg(&Xi[g]);
            float yv = __ldg(&Yi[g]);
            unsigned long long v;
            asm("mov.b64 %0, {%1, %2};" : "=l"(v) : "f"(xv), "f"(yv));
            sxy[r][c] = v;
        }
    } else {
        #pragma unroll 1
        for (int i = tid; i < SR * SCF2; i += 256) {
            int r = i / SCF2;
            int c = i - r * SCF2;
            int gr = row0 + r, gc = col0 + c;
            float xv = 0.0f, yv = 0.0f;
            if ((unsigned)gr < (unsigned)IMG && (unsigned)gc < (unsigned)IMG) {
                xv = __ldg(&Xi[gr * IMG + gc]);
                yv = __ldg(&Yi[gr * IMG + gc]);
            }
            unsigned long long v;
            asm("mov.b64 %0, {%1, %2};" : "=l"(v) : "f"(xv), "f"(yv));
            sxy[r][c] = v;
        }
    }
    __syncthreads();

    // ------- horizontal streaming FIR: 168 items x 8 outputs -------
    if (tid < SR * 4) {
        const int r  = tid % SR;       // r fastest within quarter-warp
        const int o  = tid / SR;       // 0..3
        const int c0 = o * 8;

        unsigned long long acc2[8];
        float accp[8];
        #pragma unroll
        for (int j = 0; j < 8; j++) { acc2[j] = 0ull; accp[j] = 0.0f; }

        const unsigned long long* src = &sxy[r][c0];
        #pragma unroll
        for (int q = 0; q < 9; q++) {
            ulonglong2 L = *(const ulonglong2*)(src + 2 * q);
            #pragma unroll
            for (int t = 0; t < 2; t++) {
                const int m = 2 * q + t;
                unsigned long long v = t ? L.y : L.x;
                float xl, yh;
                UNPK(xl, yh, v);
                float pm = xl * yh;
                #pragma unroll
                for (int j = 0; j < 8; j++) {
                    const int k = m - j;
                    if (k >= 0 && k <= 10) {
                        FMA2(acc2[j], v, WP[k], acc2[j]);
                        accp[j] = fmaf(WGs[k], pm, accp[j]);
                    }
                }
            }
        }
        #pragma unroll
        for (int j = 0; j < 8; j += 2)
            *(ulonglong2*)&hxy[r][c0 + j] = make_ulonglong2(acc2[j], acc2[j + 1]);
        *(float4*)&hp[r][c0]     = make_float4(accp[0], accp[1], accp[2], accp[3]);
        *(float4*)&hp[r][c0 + 4] = make_float4(accp[4], accp[5], accp[6], accp[7]);
    }
    __syncthreads();

    // ------- vertical FIR + SSIM: thread = 2 cols x 2 rows -------
    const float C1 = 0.0001f, C2 = 0.0009f;
    float lsum = 0.0f;
    {
        const int cp  = (tid & 15) * 2;   // column pair base
        const int r0v = (tid >> 4) * 2;   // row pair base

        unsigned long long a00 = 0ull, a01 = 0ull, a10 = 0ull, a11 = 0ull;
        float q00 = 0.0f, q01 = 0.0f, q10 = 0.0f, q11 = 0.0f;

        #pragma unroll
        for (int m = 0; m < 12; m++) {
            ulonglong2 L = *(const ulonglong2*)&hxy[r0v + m][cp];
            float2     P = *(const float2*)&hp[r0v + m][cp];
            if (m <= 10) {                      // j = 0, k = m
                FMA2(a00, L.x, WP[m], a00);
                FMA2(a01, L.y, WP[m], a01);
                q00 = fmaf(WGs[m], P.x, q00);
                q01 = fmaf(WGs[m], P.y, q01);
            }
            if (m >= 1) {                       // j = 1, k = m-1
                FMA2(a10, L.x, WP[m - 1], a10);
                FMA2(a11, L.y, WP[m - 1], a11);
                q10 = fmaf(WGs[m - 1], P.x, q10);
                q11 = fmaf(WGs[m - 1], P.y, q11);
            }
        }
        unsigned long long aa[4] = {a00, a01, a10, a11};
        float              qq[4] = {q00, q01, q10, q11};
        #pragma unroll
        for (int e = 0; e < 4; e++) {
            float mu1, mu2;
            UNPK(mu1, mu2, aa[e]);
            float m12 = mu1 * mu2;
            float sig = qq[e] - m12;
            float sq  = mu1 * mu1 + mu2 * mu2;
            float num = (2.0f * m12 + C1) * (2.0f * sig + C2);
            float den = (sq + C1) * (sq + C2);
            lsum += __fdividef(num, den);
        }
    }

    // ---------------- block reduction ----------------
    #pragma unroll
    for (int off = 16; off > 0; off >>= 1)
        lsum += __shfl_xor_sync(0xFFFFFFFFu, lsum, off);
    if ((tid & 31) == 0) wsum[tid >> 5] = lsum;
    __syncthreads();
    if (tid == 0) {
        float v = 0.0f;
        #pragma unroll
        for (int w = 0; w < 8; w++) v += wsum[w];
        int bid = blockIdx.x + GX * (blockIdx.y + GY * blockIdx.z);
        g_partials[bid] = v;
        __threadfence();
        unsigned int ticket = atomicAdd(&g_count, 1u);
        s_last = (ticket == NBLK - 1);
    }
    __syncthreads();

    // ---------------- last block: final reduction ----------------
    if (s_last) {
        float s = 0.0f;
        #pragma unroll 8
        for (int i = tid; i < NBLK; i += 256)
            s += *((volatile float*)&g_partials[i]);
        #pragma unroll
        for (int off = 16; off > 0; off >>= 1)
            s += __shfl_xor_sync(0xFFFFFFFFu, s, off);
        __syncthreads();
        if ((tid & 31) == 0) wsum[tid >> 5] = s;
        __syncthreads();
        if (tid == 0) {
            float v = 0.0f;
            #pragma unroll
            for (int w = 0; w < 8; w++) v += wsum[w];
            out[0]  = v * (1.0f / 8388608.0f);
            g_count = 0;
        }
    }
}

extern "C" void kernel_launch(void* const* d_in, const int* in_sizes, int n_in,
                              void* d_out, int out_size)
{
    (void)in_sizes; (void)n_in; (void)out_size;
    const float* X_gt   = (const float*)d_in[0];
    const float* X_pred = (const float*)d_in[1];
    float* out = (float*)d_out;

    dim3 grid(GX, GY, GZ);
    ssim_fused_kernel<<<grid, 256>>>(X_gt, X_pred, out);
}

// round 5
// speedup vs baseline: 1.0680x; 1.0680x over previous
#include <cuda_runtime.h>

// SSIM loss, (32,1,512,512) fp32. Single fused kernel, f32x2-packed FIR.
// R5: no input staging (h-pass reads global directly, aligned LDG.128 fast
//     path), single-phase h over 64-wide tile, single-phase v with 8-row
//     register blocking, 4 barriers/block, fused last-block mean.

#define IMG   512
#define TW    64
#define TH    32
#define SR    42          // TH + 10 h-buffer rows
#define HPIT  66          // hxy pitch (f2)
#define PPIT  68          // hp  pitch (f32)
#define GX    8
#define GY    16
#define GZ    32
#define NBLK  (GX * GY * GZ)   // 4096

__device__ float        g_partials[NBLK];
__device__ unsigned int g_count;     // zero-init; self-resets

// normalized 1D Gaussian, K=11, sigma=1.5
#define W0 0.00102838f
#define W1 0.00759876f
#define W2 0.03600077f
#define W3 0.10936060f
#define W4 0.21300553f
#define W5 0.26601172f

#define FMA2(d, a, b, c) \
    asm("fma.rn.f32x2 %0, %1, %2, %3;" : "=l"(d) : "l"(a), "l"(b), "l"(c))
#define UNPK(lo, hi, v) \
    asm("mov.b64 {%0, %1}, %2;" : "=f"(lo), "=f"(hi) : "l"(v))
#define PK(v, lo, hi) \
    asm("mov.b64 %0, {%1, %2};" : "=l"(v) : "f"(lo), "f"(hi))

__device__ __forceinline__ unsigned long long pk2(float w) {
    unsigned long long r;
    asm("mov.b64 %0, {%1, %1};" : "=l"(r) : "f"(w));
    return r;
}

__global__ __launch_bounds__(256, 5)
void ssim_fused_kernel(const float* __restrict__ X, const float* __restrict__ Y,
                       float* __restrict__ out)
{
    __shared__ unsigned long long hxy[SR][HPIT];   // h-conv packed (x,y) 21.7KB
    __shared__ float              hp [SR][PPIT];   // h-conv (x*y)        11.2KB
    __shared__ float              wsum[8];
    __shared__ int                s_last;

    const float WGs[11] = {W0, W1, W2, W3, W4, W5, W4, W3, W2, W1, W0};
    const unsigned long long p0 = pk2(W0), p1 = pk2(W1), p2 = pk2(W2),
                             p3 = pk2(W3), p4 = pk2(W4), p5 = pk2(W5);
    const unsigned long long WP[11] = {p0,p1,p2,p3,p4,p5,p4,p3,p2,p1,p0};

    const int tid  = threadIdx.x;
    const int img  = blockIdx.z;
    const int row0 = blockIdx.y * TH - 5;
    const int col0 = blockIdx.x * TW - 5;

    const float* __restrict__ Xi = X + (size_t)img * IMG * IMG;
    const float* __restrict__ Yi = Y + (size_t)img * IMG * IMG;

    const bool colsafe = (blockIdx.x >= 1) && (blockIdx.x <= 6);

    // ------- horizontal streaming FIR from GLOBAL: 336 items x 8 outputs -------
    #pragma unroll 1
    for (int i = tid; i < SR * 8; i += 256) {
        const int r  = i >> 3;
        const int o  = i & 7;
        const int c0 = o * 8;
        const int gr = row0 + r;

        unsigned long long acc2[8];
        float accp[8];
        #pragma unroll
        for (int j = 0; j < 8; j++) { acc2[j] = 0ull; accp[j] = 0.0f; }

        if ((unsigned)gr < (unsigned)IMG) {
            if (colsafe) {
                // window cols W..W+17, W = col0+c0 == 3 (mod 4); A = W-3 aligned
                const float* bx = Xi + gr * IMG + (col0 + c0 - 3);
                const float* by = Yi + gr * IMG + (col0 + c0 - 3);
                float xw[24], yw[24];
                #pragma unroll
                for (int q = 0; q < 6; q++) {
                    float4 a = __ldg((const float4*)(bx + 4 * q));
                    float4 b = __ldg((const float4*)(by + 4 * q));
                    xw[4*q+0] = a.x; xw[4*q+1] = a.y; xw[4*q+2] = a.z; xw[4*q+3] = a.w;
                    yw[4*q+0] = b.x; yw[4*q+1] = b.y; yw[4*q+2] = b.z; yw[4*q+3] = b.w;
                }
                #pragma unroll
                for (int m = 0; m < 18; m++) {
                    float xv = xw[m + 3], yv = yw[m + 3];
                    unsigned long long v;
                    PK(v, xv, yv);
                    float pm = xv * yv;
                    #pragma unroll
                    for (int j = 0; j < 8; j++) {
                        const int k = m - j;
                        if (k >= 0 && k <= 10) {
                            FMA2(acc2[j], v, WP[k], acc2[j]);
                            accp[j] = fmaf(WGs[k], pm, accp[j]);
                        }
                    }
                }
            } else {
                // boundary columns: guarded scalar loads
                const int gw = col0 + c0;
                #pragma unroll
                for (int m = 0; m < 18; m++) {
                    const int gc = gw + m;
                    float xv = 0.0f, yv = 0.0f;
                    if ((unsigned)gc < (unsigned)IMG) {
                        xv = __ldg(&Xi[gr * IMG + gc]);
                        yv = __ldg(&Yi[gr * IMG + gc]);
                    }
                    unsigned long long v;
                    PK(v, xv, yv);
                    float pm = xv * yv;
                    #pragma unroll
                    for (int j = 0; j < 8; j++) {
                        const int k = m - j;
                        if (k >= 0 && k <= 10) {
                            FMA2(acc2[j], v, WP[k], acc2[j]);
                            accp[j] = fmaf(WGs[k], pm, accp[j]);
                        }
                    }
                }
            }
        }
        // always store (zeros for OOR rows)
        #pragma unroll
        for (int j = 0; j < 8; j += 2)
            *(ulonglong2*)&hxy[r][c0 + j] = make_ulonglong2(acc2[j], acc2[j + 1]);
        *(float4*)&hp[r][c0]     = make_float4(accp[0], accp[1], accp[2], accp[3]);
        *(float4*)&hp[r][c0 + 4] = make_float4(accp[4], accp[5], accp[6], accp[7]);
    }
    __syncthreads();

    // ------- vertical streaming FIR + SSIM: col(64) x rowgroup(4), 8 rows each -------
    const float C1 = 0.0001f, C2 = 0.0009f;
    float lsum = 0.0f;
    {
        const int c   = tid & 63;
        const int r0v = (tid >> 6) * 8;

        unsigned long long acc2[8];
        float accp[8];
        #pragma unroll
        for (int j = 0; j < 8; j++) { acc2[j] = 0ull; accp[j] = 0.0f; }

        #pragma unroll
        for (int m = 0; m < 18; m++) {
            unsigned long long v = hxy[r0v + m][c];
            float pm = hp[r0v + m][c];
            #pragma unroll
            for (int j = 0; j < 8; j++) {
                const int k = m - j;
                if (k >= 0 && k <= 10) {
                    FMA2(acc2[j], v, WP[k], acc2[j]);
                    accp[j] = fmaf(WGs[k], pm, accp[j]);
                }
            }
        }
        #pragma unroll
        for (int j = 0; j < 8; j++) {
            float mu1, mu2;
            UNPK(mu1, mu2, acc2[j]);
            float m12 = mu1 * mu2;
            float sig = accp[j] - m12;
            float sq  = mu1 * mu1 + mu2 * mu2;
            float num = (2.0f * m12 + C1) * (2.0f * sig + C2);
            float den = (sq + C1) * (sq + C2);
            lsum += __fdividef(num, den);
        }
    }

    // ---------------- block reduction ----------------
    #pragma unroll
    for (int off = 16; off > 0; off >>= 1)
        lsum += __shfl_xor_sync(0xFFFFFFFFu, lsum, off);
    if ((tid & 31) == 0) wsum[tid >> 5] = lsum;
    __syncthreads();
    if (tid == 0) {
        float v = 0.0f;
        #pragma unroll
        for (int w = 0; w < 8; w++) v += wsum[w];
        int bid = blockIdx.x + GX * (blockIdx.y + GY * blockIdx.z);
        g_partials[bid] = v;
        __threadfence();
        unsigned int ticket = atomicAdd(&g_count, 1u);
        s_last = (ticket == NBLK - 1);
    }
    __syncthreads();

    // ---------------- last block: final reduction ----------------
    if (s_last) {
        float s = 0.0f;
        #pragma unroll 4
        for (int i = tid; i < NBLK; i += 256)
            s += *((volatile float*)&g_partials[i]);
        #pragma unroll
        for (int off = 16; off > 0; off >>= 1)
            s += __shfl_xor_sync(0xFFFFFFFFu, s, off);
        __syncthreads();
        if ((tid & 31) == 0) wsum[tid >> 5] = s;
        __syncthreads();
        if (tid == 0) {
            float v = 0.0f;
            #pragma unroll
            for (int w = 0; w < 8; w++) v += wsum[w];
            out[0]  = v * (1.0f / 8388608.0f);
            g_count = 0;
        }
    }
}

extern "C" void kernel_launch(void* const* d_in, const int* in_sizes, int n_in,
                              void* d_out, int out_size)
{
    (void)in_sizes; (void)n_in; (void)out_size;
    const float* X_gt   = (const float*)d_in[0];
    const float* X_pred = (const float*)d_in[1];
    float* out = (float*)d_out;

    dim3 grid(GX, GY, GZ);
    ssim_fused_kernel<<<grid, 256>>>(X_gt, X_pred, out);
}